// round 16
// baseline (speedup 1.0000x reference)
#include <cuda_runtime.h>
#include <cuda_bf16.h>
#include <cstdint>
#include <math.h>

#define HW 4096
#define Tn 50

typedef uint32_t u32;
typedef unsigned short u16;

// Scratch (static __device__ arrays — allocation-free per harness rules)
__device__ float g_XC[400u * 128u * 4096u];   // [t*8+b][128][4096]
__device__ float g_yconv[8 * 96 * 4096];
__device__ float g_Y[8 * 32 * 4096];
__device__ float g_Zbuf[2][8 * 32 * 4096];    // ping-pong Z (race-free fusion)

#define KPAD   296            // u16 elements per weight row (288 used)
#define KPAD32 (KPAD / 2)
// Packed bf16 hi/lo weights: rows 0..127 = Wx, 128..223 = Wy, 224..255 = Wz
__device__ u16 g_WH[256 * KPAD];
__device__ u16 g_WL[256 * KPAD];

__device__ __forceinline__ float fsigmoid(float x) {
    return 1.0f / (1.0f + __expf(-x));
}
__device__ __forceinline__ float ftanh(float x) {
    x = fminf(fmaxf(x, -12.0f), 12.0f);
    float e = __expf(2.0f * x);
    return 1.0f - 2.0f / (e + 1.0f);
}

// mma.sync m16n8k16 bf16 (baseline PTX, sm_80+; tensor pipe)
__device__ __forceinline__ void mma16816(float* d,
                                         u32 a0, u32 a1, u32 a2, u32 a3,
                                         u32 b0, u32 b1) {
    asm volatile(
        "mma.sync.aligned.m16n8k16.row.col.f32.bf16.bf16.f32 "
        "{%0,%1,%2,%3}, {%4,%5,%6,%7}, {%8,%9}, {%0,%1,%2,%3};"
        : "+f"(d[0]), "+f"(d[1]), "+f"(d[2]), "+f"(d[3])
        : "r"(a0), "r"(a1), "r"(a2), "r"(a3), "r"(b0), "r"(b1));
}

// ---------------------------------------------------------------------------
// One-time weight prep: float -> bf16 hi/lo, layout [row][k], k = tap*32 + ci
// ---------------------------------------------------------------------------
__global__ void prep_w(const float* __restrict__ Wx,
                       const float* __restrict__ Wy,
                       const float* __restrict__ Wz)
{
    int idx = blockIdx.x * 256 + threadIdx.x;
    if (idx >= 256 * KPAD) return;
    int row = idx / KPAD, k = idx - row * KPAD;
    u16 h = 0, l = 0;
    if (k < 288) {
        int tap = k >> 5, ci = k & 31;
        const float* W; int co;
        if (row < 128)      { W = Wx; co = row; }
        else if (row < 224) { W = Wy; co = row - 128; }
        else                { W = Wz; co = row - 224; }
        float w = W[((size_t)co * 32 + ci) * 9 + tap];
        __nv_bfloat16 wh = __float2bfloat16(w);
        __nv_bfloat16 wl = __float2bfloat16(w - __bfloat162float(wh));
        h = __bfloat16_as_ushort(wh);
        l = __bfloat16_as_ushort(wl);
    }
    g_WH[idx] = h;
    g_WL[idx] = l;
}

// ---------------------------------------------------------------------------
// Shared-memory layout (conv_tc: 32 co per CTA) — R11-proven, 101 KB, 2 CTA/SM
// ---------------------------------------------------------------------------
#define CIPAD   40
#define AELEMS  (6 * 66 * CIPAD)                 // 15840
#define OFF_AH  0
#define OFF_AL  (AELEMS * 2)                     // 31680
#define OFF_WH  (OFF_AL + AELEMS * 2)            // 63360
#define OFF_WL  (OFF_WH + 32 * KPAD * 2)
#define OFF_BI  (OFF_WL + 32 * KPAD * 2)
#define SMEM_SZ (OFF_BI + 128)                   // ~101.4 KB

// ---------------------------------------------------------------------------
// conv_tc: 3x3 SAME conv, Cin=32, 32 co per CTA.
// MODE 0: X -> g_XC      (grid = 16 x 4 x 400)
// MODE 1: g_Y -> g_yconv (grid = 16 x 3 x 8)   [R11-proven split form]
// ---------------------------------------------------------------------------
template<int MODE>
__global__ void __launch_bounds__(256, 2)
conv_tc(const float* __restrict__ X,
        const u16* __restrict__ gWh,   // pre-sliced for this conv
        const u16* __restrict__ gWl,
        const float* __restrict__ bias,
        int t)
{
    extern __shared__ char smem[];
    u16*   sAh   = (u16*)(smem + OFF_AH);
    u16*   sAl   = (u16*)(smem + OFF_AL);
    u16*   sWh   = (u16*)(smem + OFF_WH);
    u16*   sWl   = (u16*)(smem + OFF_WL);
    float* sBias = (float*)(smem + OFF_BI);

    const int tid   = threadIdx.x;
    const int ytile = blockIdx.x;        // 4 image rows each
    const int cog   = blockIdx.y;
    const int img   = blockIdx.z;

    int b, ti;
    if (MODE == 0) { b = img & 7; ti = img >> 3; }
    else           { b = img;     ti = t; }

    const float* src;
    size_t in_base; int chstride;
    if (MODE == 0) { src = X;   in_base = ((size_t)b * 32 * Tn + ti) * HW; chstride = Tn * HW; }
    else           { src = g_Y; in_base = (size_t)b * 32 * HW; chstride = HW; }

    const int y0 = ytile * 4;

    // ---- stage weights: straight u32 copy from prepped arrays ----
    {
        const u32* wh32 = (const u32*)gWh + (size_t)cog * 32 * KPAD32;
        const u32* wl32 = (const u32*)gWl + (size_t)cog * 32 * KPAD32;
        for (int e = tid; e < 32 * KPAD32; e += 256) {
            ((u32*)sWh)[e] = wh32[e];
            ((u32*)sWl)[e] = wl32[e];
        }
    }
    if (tid < 32) sBias[tid] = bias[cog * 32 + tid];

    // ---- stage halo tile [6][66][ci] channel-major, SAME zero-padding ----
    for (int e = tid; e < 32 * 6 * 66; e += 256) {
        int ci = e / 396, r = e - ci * 396;
        int hy = r / 66,  hx = r - hy * 66;
        int gy = y0 - 1 + hy, gx = hx - 1;
        float v = 0.0f;
        if ((unsigned)gy < 64u && (unsigned)gx < 64u)
            v = src[in_base + (size_t)ci * chstride + gy * 64 + gx];
        __nv_bfloat16 h = __float2bfloat16(v);
        __nv_bfloat16 l = __float2bfloat16(v - __bfloat162float(h));
        int slot = (hy * 66 + hx) * CIPAD + ci;
        sAh[slot] = __bfloat16_as_ushort(h);
        sAl[slot] = __bfloat16_as_ushort(l);
    }
    __syncthreads();

    // ---- warp GEMM: M=32, N=32 ----
    const int wid  = tid >> 5;
    const int lane = tid & 31;
    const int gid  = lane >> 2;
    const int tig  = lane & 3;
    const int m0   = wid * 32;

    int abase[4];
#pragma unroll
    for (int r = 0; r < 4; r++) {
        int m  = m0 + r * 8 + gid;
        int py = m >> 6, px = m & 63;
        abase[r] = (py * 66 + px) * CIPAD + tig * 2;
    }
    int bbase[4];
#pragma unroll
    for (int nf = 0; nf < 4; nf++)
        bbase[nf] = (nf * 8 + gid) * KPAD + tig * 2;

    float acc[2][4][4];
#pragma unroll
    for (int mf = 0; mf < 2; mf++)
#pragma unroll
        for (int nf = 0; nf < 4; nf++)
#pragma unroll
            for (int i = 0; i < 4; i++) acc[mf][nf][i] = 0.0f;

#pragma unroll 1
    for (int tap = 0; tap < 9; tap++) {
        const int dy = tap / 3, dx = tap - dy * 3;
        const int aofs_t = (dy * 66 + dx) * CIPAD;
        const int bofs_t = tap * 32;
#pragma unroll
        for (int kc = 0; kc < 2; kc++) {
            const int aofs = aofs_t + kc * 16;
            const int bofs = bofs_t + kc * 16;

            u32 Ah[2][4], Al[2][4];
#pragma unroll
            for (int mf = 0; mf < 2; mf++) {
                int i0 = abase[2 * mf]     + aofs;
                int i1 = abase[2 * mf + 1] + aofs;
                Ah[mf][0] = *(const u32*)&sAh[i0];
                Ah[mf][1] = *(const u32*)&sAh[i1];
                Ah[mf][2] = *(const u32*)&sAh[i0 + 8];
                Ah[mf][3] = *(const u32*)&sAh[i1 + 8];
                Al[mf][0] = *(const u32*)&sAl[i0];
                Al[mf][1] = *(const u32*)&sAl[i1];
                Al[mf][2] = *(const u32*)&sAl[i0 + 8];
                Al[mf][3] = *(const u32*)&sAl[i1 + 8];
            }
#pragma unroll
            for (int nf = 0; nf < 4; nf++) {
                int j = bbase[nf] + bofs;
                u32 Bh0 = *(const u32*)&sWh[j];
                u32 Bh1 = *(const u32*)&sWh[j + 8];
                u32 Bl0 = *(const u32*)&sWl[j];
                u32 Bl1 = *(const u32*)&sWl[j + 8];
#pragma unroll
                for (int mf = 0; mf < 2; mf++) {
                    mma16816(acc[mf][nf], Ah[mf][0], Ah[mf][1], Ah[mf][2], Ah[mf][3], Bh0, Bh1);
                    mma16816(acc[mf][nf], Al[mf][0], Al[mf][1], Al[mf][2], Al[mf][3], Bh0, Bh1);
                    mma16816(acc[mf][nf], Ah[mf][0], Ah[mf][1], Ah[mf][2], Ah[mf][3], Bl0, Bl1);
                }
            }
        }
    }

    // ---- epilogue ----
#pragma unroll
    for (int mf = 0; mf < 2; mf++) {
#pragma unroll
        for (int nf = 0; nf < 4; nf++) {
#pragma unroll
            for (int i = 0; i < 4; i++) {
                int m   = m0 + mf * 16 + gid + (i >> 1) * 8;
                int n   = nf * 8 + tig * 2 + (i & 1);
                int pix = ytile * 256 + m;
                int co  = cog * 32 + n;
                float v = acc[mf][nf][i] + sBias[n];
                if (MODE == 0) {
                    g_XC[((size_t)img * 128 + co) * HW + pix] = v;
                } else {
                    g_yconv[((size_t)b * 96 + co) * HW + pix] = v;
                }
            }
        }
    }
}

// ---------------------------------------------------------------------------
// convZ_k: fused [elementwise Z-update] + [conv(Z_new, Wz)] + [Y update].
// Prologue computes Z_new for every halo pixel from yconv/XC/Z_old (redundant
// across neighbor CTAs; race-free because Z_old is a read-only ping-pong
// buffer), stages it as the bf16 hi/lo A tile, stores sigmoid gate G2 for
// interior pixels in smem, writes Z_new interior to the other Z buffer.
// Then the standard warp GEMM (32 co) and a fused Y-update epilogue.
// grid = (16 ytiles, 8 batch), 256 threads.
// ---------------------------------------------------------------------------
#define ZOFF_WH  (AELEMS * 4)                    // 63360
#define ZOFF_WL  (ZOFF_WH + 32 * KPAD * 2)
#define ZOFF_G2  (ZOFF_WL + 32 * KPAD * 2)       // 101248
#define ZOFF_BI  (ZOFF_G2 + 32 * 256 * 4)        // 134016
#define ZSMEM_SZ (ZOFF_BI + 256)                 // ~134.3 KB

__global__ void __launch_bounds__(256)
convZ_k(const u16* __restrict__ gWh,
        const u16* __restrict__ gWl,
        const float* __restrict__ bz,
        const float* __restrict__ Zold,
        float* __restrict__ Znew,
        float* __restrict__ out,
        int t)
{
    extern __shared__ char smem[];
    u16*   sAh   = (u16*)(smem);
    u16*   sAl   = (u16*)(smem + AELEMS * 2);
    u16*   sWh   = (u16*)(smem + ZOFF_WH);
    u16*   sWl   = (u16*)(smem + ZOFF_WL);
    float* sG2   = (float*)(smem + ZOFF_G2);     // [32 c][256 pix]
    float* sBias = (float*)(smem + ZOFF_BI);

    const int tid   = threadIdx.x;
    const int ytile = blockIdx.x;
    const int b     = blockIdx.y;
    const int y0    = ytile * 4;

    // ---- stage weights (Wz slice) ----
    {
        const u32* wh32 = (const u32*)gWh;
        const u32* wl32 = (const u32*)gWl;
        for (int e = tid; e < 32 * KPAD32; e += 256) {
            ((u32*)sWh)[e] = wh32[e];
            ((u32*)sWl)[e] = wl32[e];
        }
    }
    if (tid < 32) sBias[tid] = bz[tid];

    // ---- fused Z-update + halo staging ----
    for (int e = tid; e < 32 * 6 * 66; e += 256) {
        int ci = e / 396, r = e - ci * 396;
        int hy = r / 66,  hx = r - hy * 66;
        int gy = y0 - 1 + hy, gx = hx - 1;
        float zn = 0.0f;
        if ((unsigned)gy < 64u && (unsigned)gx < 64u) {
            int pix = gy * 64 + gx;
            size_t off = ((size_t)b * 32 + ci) * HW + pix;
            size_t xb  = (((size_t)(t * 8 + b)) * 128 + ci) * HW + pix;
            size_t yb  = ((size_t)b * 96 + ci) * HW + pix;
            float a1 = g_XC[xb]           + g_yconv[yb];
            float a2 = g_XC[xb + 32 * HW] + g_yconv[yb + 32 * HW];
            float az = g_XC[xb + 64 * HW] + g_yconv[yb + 64 * HW];
            float ms1 = fsigmoid(a1);
            float zv  = Zold[off];
            zn = fmaf(ms1, ftanh(az) - zv, zv);
            // interior pixel of this CTA tile?
            if (hy >= 1 && hy <= 4 && hx >= 1 && hx <= 64) {
                Znew[off] = zn;
                sG2[ci * 256 + (gy - y0) * 64 + gx] = fsigmoid(a2);
            }
        }
        __nv_bfloat16 h = __float2bfloat16(zn);
        __nv_bfloat16 l = __float2bfloat16(zn - __bfloat162float(h));
        int slot = (hy * 66 + hx) * CIPAD + ci;
        sAh[slot] = __bfloat16_as_ushort(h);
        sAl[slot] = __bfloat16_as_ushort(l);
    }
    __syncthreads();

    // ---- warp GEMM: M=32, N=32 ----
    const int wid  = tid >> 5;
    const int lane = tid & 31;
    const int gid  = lane >> 2;
    const int tig  = lane & 3;
    const int m0   = wid * 32;

    int abase[4];
#pragma unroll
    for (int r = 0; r < 4; r++) {
        int m  = m0 + r * 8 + gid;
        int py = m >> 6, px = m & 63;
        abase[r] = (py * 66 + px) * CIPAD + tig * 2;
    }
    int bbase[4];
#pragma unroll
    for (int nf = 0; nf < 4; nf++)
        bbase[nf] = (nf * 8 + gid) * KPAD + tig * 2;

    float acc[2][4][4];
#pragma unroll
    for (int mf = 0; mf < 2; mf++)
#pragma unroll
        for (int nf = 0; nf < 4; nf++)
#pragma unroll
            for (int i = 0; i < 4; i++) acc[mf][nf][i] = 0.0f;

#pragma unroll 1
    for (int tap = 0; tap < 9; tap++) {
        const int dy = tap / 3, dx = tap - dy * 3;
        const int aofs_t = (dy * 66 + dx) * CIPAD;
        const int bofs_t = tap * 32;
#pragma unroll
        for (int kc = 0; kc < 2; kc++) {
            const int aofs = aofs_t + kc * 16;
            const int bofs = bofs_t + kc * 16;

            u32 Ah[2][4], Al[2][4];
#pragma unroll
            for (int mf = 0; mf < 2; mf++) {
                int i0 = abase[2 * mf]     + aofs;
                int i1 = abase[2 * mf + 1] + aofs;
                Ah[mf][0] = *(const u32*)&sAh[i0];
                Ah[mf][1] = *(const u32*)&sAh[i1];
                Ah[mf][2] = *(const u32*)&sAh[i0 + 8];
                Ah[mf][3] = *(const u32*)&sAh[i1 + 8];
                Al[mf][0] = *(const u32*)&sAl[i0];
                Al[mf][1] = *(const u32*)&sAl[i1];
                Al[mf][2] = *(const u32*)&sAl[i0 + 8];
                Al[mf][3] = *(const u32*)&sAl[i1 + 8];
            }
#pragma unroll
            for (int nf = 0; nf < 4; nf++) {
                int j = bbase[nf] + bofs;
                u32 Bh0 = *(const u32*)&sWh[j];
                u32 Bh1 = *(const u32*)&sWh[j + 8];
                u32 Bl0 = *(const u32*)&sWl[j];
                u32 Bl1 = *(const u32*)&sWl[j + 8];
#pragma unroll
                for (int mf = 0; mf < 2; mf++) {
                    mma16816(acc[mf][nf], Ah[mf][0], Ah[mf][1], Ah[mf][2], Ah[mf][3], Bh0, Bh1);
                    mma16816(acc[mf][nf], Al[mf][0], Al[mf][1], Al[mf][2], Al[mf][3], Bh0, Bh1);
                    mma16816(acc[mf][nf], Ah[mf][0], Ah[mf][1], Ah[mf][2], Ah[mf][3], Bl0, Bl1);
                }
            }
        }
    }

    // ---- fused Y-update epilogue ----
#pragma unroll
    for (int mf = 0; mf < 2; mf++) {
#pragma unroll
        for (int nf = 0; nf < 4; nf++) {
#pragma unroll
            for (int i = 0; i < 4; i++) {
                int m   = m0 + mf * 16 + gid + (i >> 1) * 8;
                int n   = nf * 8 + tig * 2 + (i & 1);
                int pix = ytile * 256 + m;
                float v  = acc[mf][nf][i] + sBias[n];
                float g2 = sG2[n * 256 + m];
                size_t off = ((size_t)b * 32 + n) * HW + pix;
                float xy = g_XC[(((size_t)(t * 8 + b)) * 128 + 96 + n) * HW + pix];
                float yv = g_Y[off];
                float yn = fmaf(g2, ftanh(xy + v) - yv, yv);
                g_Y[off] = yn;
                out[((size_t)(b * 32 + n) * Tn + t) * HW + pix] = yn;
            }
        }
    }
}

__global__ void init_k()
{
    int idx = blockIdx.x * blockDim.x + threadIdx.x;
    if (idx < 8 * 32 * 4096) { g_Y[idx] = 0.0f; g_Zbuf[0][idx] = 0.0f; }
}

extern "C" void kernel_launch(void* const* d_in, const int* in_sizes, int n_in,
                              void* d_out, int out_size)
{
    const float* X  = (const float*)d_in[0];
    const float* Wx = (const float*)d_in[1];
    const float* bx = (const float*)d_in[2];
    const float* Wy = (const float*)d_in[3];
    const float* by = (const float*)d_in[4];
    const float* Wz = (const float*)d_in[5];
    const float* bz = (const float*)d_in[6];
    float* out = (float*)d_out;

    static bool attr_done = false;
    if (!attr_done) {
        cudaFuncSetAttribute(conv_tc<0>, cudaFuncAttributeMaxDynamicSharedMemorySize, SMEM_SZ);
        cudaFuncSetAttribute(conv_tc<1>, cudaFuncAttributeMaxDynamicSharedMemorySize, SMEM_SZ);
        cudaFuncSetAttribute(convZ_k,    cudaFuncAttributeMaxDynamicSharedMemorySize, ZSMEM_SZ);
        attr_done = true;
    }

    u16* WH = nullptr; u16* WL = nullptr;
    float* Zb = nullptr;
    cudaGetSymbolAddress((void**)&WH, g_WH);
    cudaGetSymbolAddress((void**)&WL, g_WL);
    cudaGetSymbolAddress((void**)&Zb, g_Zbuf);
    const size_t ZN = (size_t)8 * 32 * 4096;

    // Per-replay prep (deterministic): weights -> bf16 hi/lo; reset state.
    prep_w<<<(256 * KPAD + 255) / 256, 256>>>(Wx, Wy, Wz);
    init_k<<<(8 * 32 * 4096 + 255) / 256, 256>>>();

    // Precompute all input convolutions (tensor cores).
    conv_tc<0><<<dim3(16, 4, 400), 256, SMEM_SZ>>>(X, WH, WL, bx, 0);

    // Recurrence: 50 steps, 2 launches each.
    const u16* WyH = WH + (size_t)128 * KPAD;
    const u16* WyL = WL + (size_t)128 * KPAD;
    const u16* WzH = WH + (size_t)224 * KPAD;
    const u16* WzL = WL + (size_t)224 * KPAD;
    for (int t = 0; t < Tn; t++) {
        conv_tc<1><<<dim3(16, 3, 8), 256, SMEM_SZ>>>(nullptr, WyH, WyL, by, t);
        const float* Zold = Zb + (size_t)(t & 1) * ZN;
        float*       Znew = Zb + (size_t)((t + 1) & 1) * ZN;
        convZ_k<<<dim3(16, 8), 256, ZSMEM_SZ>>>(WzH, WzL, bz, Zold, Znew, out, t);
    }
}

// round 17
// speedup vs baseline: 1.3759x; 1.3759x over previous
#include <cuda_runtime.h>
#include <cuda_bf16.h>
#include <cstdint>
#include <math.h>

#define HW 4096
#define Tn 50

typedef uint32_t u32;
typedef unsigned short u16;

// Scratch (static __device__ arrays — allocation-free per harness rules)
__device__ float g_XC[400u * 128u * 4096u];   // [t*8+b][128][4096]
__device__ float g_yconv[8 * 96 * 4096];
__device__ float g_Y[8 * 32 * 4096];
__device__ float g_Z[8 * 32 * 4096];
__device__ float g_G2[8 * 32 * 4096];

#define KPAD   296            // u16 elements per weight row (288 used)
#define KPAD32 (KPAD / 2)
// Packed bf16 hi/lo weights: rows 0..127 = Wx, 128..223 = Wy, 224..255 = Wz
__device__ u16 g_WH[256 * KPAD];
__device__ u16 g_WL[256 * KPAD];

__device__ __forceinline__ float fsigmoid(float x) {
    return 1.0f / (1.0f + __expf(-x));
}
__device__ __forceinline__ float ftanh(float x) {
    x = fminf(fmaxf(x, -12.0f), 12.0f);
    float e = __expf(2.0f * x);
    return 1.0f - 2.0f / (e + 1.0f);
}

// mma.sync m16n8k16 bf16 (baseline PTX, sm_80+; tensor pipe)
__device__ __forceinline__ void mma16816(float* d,
                                         u32 a0, u32 a1, u32 a2, u32 a3,
                                         u32 b0, u32 b1) {
    asm volatile(
        "mma.sync.aligned.m16n8k16.row.col.f32.bf16.bf16.f32 "
        "{%0,%1,%2,%3}, {%4,%5,%6,%7}, {%8,%9}, {%0,%1,%2,%3};"
        : "+f"(d[0]), "+f"(d[1]), "+f"(d[2]), "+f"(d[3])
        : "r"(a0), "r"(a1), "r"(a2), "r"(a3), "r"(b0), "r"(b1));
}

// ldmatrix x4 (baseline PTX, sm_75+): four 8x8 b16 tiles
#define LDSM_X4(r, addr) \
    asm volatile("ldmatrix.sync.aligned.m8n8.x4.shared.b16 {%0,%1,%2,%3}, [%4];" \
        : "=r"((r)[0]), "=r"((r)[1]), "=r"((r)[2]), "=r"((r)[3]) : "r"(addr))

__device__ __forceinline__ u32 smem_u32(const void* p) {
    u32 a;
    asm("{ .reg .u64 t; cvta.to.shared.u64 t, %1; cvt.u32.u64 %0, t; }"
        : "=r"(a) : "l"(p));
    return a;
}

// ---------------------------------------------------------------------------
// One-time weight prep: float -> bf16 hi/lo, layout [row][k], k = tap*32 + ci
// ---------------------------------------------------------------------------
__global__ void prep_w(const float* __restrict__ Wx,
                       const float* __restrict__ Wy,
                       const float* __restrict__ Wz)
{
    int idx = blockIdx.x * 256 + threadIdx.x;
    if (idx >= 256 * KPAD) return;
    int row = idx / KPAD, k = idx - row * KPAD;
    u16 h = 0, l = 0;
    if (k < 288) {
        int tap = k >> 5, ci = k & 31;
        const float* W; int co;
        if (row < 128)      { W = Wx; co = row; }
        else if (row < 224) { W = Wy; co = row - 128; }
        else                { W = Wz; co = row - 224; }
        float w = W[((size_t)co * 32 + ci) * 9 + tap];
        __nv_bfloat16 wh = __float2bfloat16(w);
        __nv_bfloat16 wl = __float2bfloat16(w - __bfloat162float(wh));
        h = __bfloat16_as_ushort(wh);
        l = __bfloat16_as_ushort(wl);
    }
    g_WH[idx] = h;
    g_WL[idx] = l;
}

// ---------------------------------------------------------------------------
// Shared-memory layout (conv_tc: 32 co per CTA) — 101 KB, 2 CTA/SM
// ---------------------------------------------------------------------------
#define CIPAD   40
#define AELEMS  (6 * 66 * CIPAD)                 // 15840
#define OFF_AH  0
#define OFF_AL  (AELEMS * 2)                     // 31680
#define OFF_WH  (OFF_AL + AELEMS * 2)            // 63360
#define WSLICE  (32 * KPAD * 2)                  // 18944
#define OFF_WL  (OFF_WH + WSLICE)
#define OFF_BI  (OFF_WL + WSLICE)
#define SMEM_SZ (OFF_BI + 128)                   // ~101.4 KB

// ---------------------------------------------------------------------------
// conv_tc: 3x3 SAME conv, Cin=32, 32 co per CTA, LDSM fragment loads.
// MODE 0: X -> g_XC      (grid = 16 x 4 x 400)
// MODE 1: g_Y -> g_yconv (grid = 16 x 3 x 8)
// MODE 2: g_Z -> fused Y update -> g_Y and out (grid = 16 x 1 x 8)
// ---------------------------------------------------------------------------
template<int MODE>
__global__ void __launch_bounds__(256, 2)
conv_tc(const float* __restrict__ X,
        const u16* __restrict__ gWh,   // pre-sliced for this conv
        const u16* __restrict__ gWl,
        const float* __restrict__ bias,
        float* __restrict__ out,
        int t)
{
    extern __shared__ char smem[];
    u16*   sAh   = (u16*)(smem + OFF_AH);
    u16*   sAl   = (u16*)(smem + OFF_AL);
    float* sBias = (float*)(smem + OFF_BI);
    const u32 sbase = smem_u32(smem);

    const int tid   = threadIdx.x;
    const int ytile = blockIdx.x;        // 4 image rows each
    const int cog   = blockIdx.y;
    const int img   = blockIdx.z;

    int b, ti;
    if (MODE == 0) { b = img & 7; ti = img >> 3; }
    else           { b = img;     ti = t; }

    const float* src;
    size_t in_base; int chstride;
    if (MODE == 0)      { src = X;   in_base = ((size_t)b * 32 * Tn + ti) * HW; chstride = Tn * HW; }
    else if (MODE == 1) { src = g_Y; in_base = (size_t)b * 32 * HW; chstride = HW; }
    else                { src = g_Z; in_base = (size_t)b * 32 * HW; chstride = HW; }

    const int y0 = ytile * 4;

    // ---- stage weights: straight u32 copy from prepped arrays ----
    {
        const u32* wh32 = (const u32*)gWh + (size_t)cog * 32 * KPAD32;
        const u32* wl32 = (const u32*)gWl + (size_t)cog * 32 * KPAD32;
        u32* dWh = (u32*)(smem + OFF_WH);
        u32* dWl = (u32*)(smem + OFF_WL);
        for (int e = tid; e < 32 * KPAD32; e += 256) {
            dWh[e] = wh32[e];
            dWl[e] = wl32[e];
        }
    }
    if (tid < 32) sBias[tid] = bias[cog * 32 + tid];

    // ---- stage halo tile [6][66][ci] channel-major, SAME zero-padding ----
    for (int e = tid; e < 32 * 6 * 66; e += 256) {
        int ci = e / 396, r = e - ci * 396;
        int hy = r / 66,  hx = r - hy * 66;
        int gy = y0 - 1 + hy, gx = hx - 1;
        float v = 0.0f;
        if ((unsigned)gy < 64u && (unsigned)gx < 64u)
            v = src[in_base + (size_t)ci * chstride + gy * 64 + gx];
        __nv_bfloat16 h = __float2bfloat16(v);
        __nv_bfloat16 l = __float2bfloat16(v - __bfloat162float(h));
        int slot = (hy * 66 + hx) * CIPAD + ci;
        sAh[slot] = __bfloat16_as_ushort(h);
        sAl[slot] = __bfloat16_as_ushort(l);
    }
    __syncthreads();

    // ---- warp GEMM: M=32, N=32, ldmatrix fragment loads ----
    const int wid  = tid >> 5;
    const int lane = tid & 31;
    const int gid  = lane >> 2;
    const int tig  = lane & 3;
    const int m0   = wid * 32;

    // per-lane LDSM base byte-addresses
    u32 aAddr[2];
    {
        int mr = m0 + (lane & 15);
#pragma unroll
        for (int mf = 0; mf < 2; mf++) {
            int m  = mr + mf * 16;
            int py = m >> 6, px = m & 63;
            aAddr[mf] = sbase + OFF_AH + ((py * 66 + px) * CIPAD) * 2
                      + ((lane >> 4) * 16);
        }
    }
    u32 bAddr[2];
    {
        int rr = (lane & 7) + ((lane >> 4) << 3);   // row within 16-row group
#pragma unroll
        for (int p = 0; p < 2; p++) {
            int row = p * 16 + rr;
            bAddr[p] = sbase + OFF_WH + (row * KPAD) * 2
                     + (((lane >> 3) & 1) * 16);
        }
    }

    float acc[2][4][4];
#pragma unroll
    for (int mf = 0; mf < 2; mf++)
#pragma unroll
        for (int nf = 0; nf < 4; nf++)
#pragma unroll
            for (int i = 0; i < 4; i++) acc[mf][nf][i] = 0.0f;

#pragma unroll 1
    for (int tap = 0; tap < 9; tap++) {
        const int dy = tap / 3, dx = tap - dy * 3;
        const int aofs_t = (dy * 66 + dx) * CIPAD;
        const int bofs_t = tap * 32;
#pragma unroll
        for (int kc = 0; kc < 2; kc++) {
            const u32 aofs2 = (u32)(aofs_t + kc * 16) * 2;
            const u32 bofs2 = (u32)(bofs_t + kc * 16) * 2;

            u32 Ah[2][4], Al[2][4], Bh[2][4], Bl[2][4];
#pragma unroll
            for (int mf = 0; mf < 2; mf++) {
                LDSM_X4(Ah[mf], aAddr[mf] + aofs2);
                LDSM_X4(Al[mf], aAddr[mf] + aofs2 + (u32)(AELEMS * 2));
            }
#pragma unroll
            for (int p = 0; p < 2; p++) {
                LDSM_X4(Bh[p], bAddr[p] + bofs2);
                LDSM_X4(Bl[p], bAddr[p] + bofs2 + (u32)WSLICE);
            }
#pragma unroll
            for (int nf = 0; nf < 4; nf++) {
                const int p = nf >> 1, q = (nf & 1) * 2;
                u32 Bh0 = Bh[p][q], Bh1 = Bh[p][q + 1];
                u32 Bl0 = Bl[p][q], Bl1 = Bl[p][q + 1];
#pragma unroll
                for (int mf = 0; mf < 2; mf++) {
                    mma16816(acc[mf][nf], Ah[mf][0], Ah[mf][1], Ah[mf][2], Ah[mf][3], Bh0, Bh1);
                    mma16816(acc[mf][nf], Al[mf][0], Al[mf][1], Al[mf][2], Al[mf][3], Bh0, Bh1);
                    mma16816(acc[mf][nf], Ah[mf][0], Ah[mf][1], Ah[mf][2], Ah[mf][3], Bl0, Bl1);
                }
            }
        }
    }

    // ---- epilogue ----
#pragma unroll
    for (int mf = 0; mf < 2; mf++) {
#pragma unroll
        for (int nf = 0; nf < 4; nf++) {
#pragma unroll
            for (int i = 0; i < 4; i++) {
                int m   = m0 + mf * 16 + gid + (i >> 1) * 8;
                int n   = nf * 8 + tig * 2 + (i & 1);
                int pix = ytile * 256 + m;
                int co  = cog * 32 + n;
                float v = acc[mf][nf][i] + sBias[n];
                if (MODE == 0) {
                    g_XC[((size_t)img * 128 + co) * HW + pix] = v;
                } else if (MODE == 1) {
                    g_yconv[((size_t)b * 96 + co) * HW + pix] = v;
                } else {
                    size_t off = ((size_t)b * 32 + co) * HW + pix;
                    float g2 = g_G2[off];
                    float xy = g_XC[(((size_t)(t * 8 + b)) * 128 + 96 + co) * HW + pix];
                    float yv = g_Y[off];
                    float yn = fmaf(g2, ftanh(xy + v) - yv, yv);
                    g_Y[off] = yn;
                    out[((size_t)(b * 32 + co) * Tn + t) * HW + pix] = yn;
                }
            }
        }
    }
}

// ---------------------------------------------------------------------------
// Elementwise (float4): ms1 gate, Z update, precompute G2 gate for Y update.
// ---------------------------------------------------------------------------
__global__ void elemZ_k(int t)
{
    int i4 = blockIdx.x * blockDim.x + threadIdx.x;
    if (i4 >= (8 * 32 * 4096) / 4) return;
    int b   = i4 >> 15;
    int rem = i4 & 32767;
    int c   = rem >> 10;
    int p4  = rem & 1023;

    const float4* yc = (const float4*)g_yconv + ((size_t)b * 96 + c) * (HW / 4) + p4;
    const float4* xc = (const float4*)g_XC + (((size_t)(t * 8 + b)) * 128 + c) * (HW / 4) + p4;
    float4 yc1 = yc[0];
    float4 yc2 = yc[32 * HW / 4];
    float4 yc3 = yc[64 * HW / 4];
    float4 x1  = xc[0];
    float4 x2  = xc[32 * HW / 4];
    float4 x3  = xc[64 * HW / 4];

    float4 zv = ((const float4*)g_Z)[i4];
    float4 zn, g2;
#pragma unroll
    for (int k = 0; k < 4; k++) {
        float a1 = ((&x1.x)[k]) + ((&yc1.x)[k]);
        float a2 = ((&x2.x)[k]) + ((&yc2.x)[k]);
        float az = ((&x3.x)[k]) + ((&yc3.x)[k]);
        float ms1 = fsigmoid(a1);
        float z0  = (&zv.x)[k];
        (&zn.x)[k] = fmaf(ms1, ftanh(az) - z0, z0);
        (&g2.x)[k] = fsigmoid(a2);
    }
    ((float4*)g_Z)[i4]  = zn;
    ((float4*)g_G2)[i4] = g2;
}

__global__ void init_k()
{
    int idx = blockIdx.x * blockDim.x + threadIdx.x;
    if (idx < 8 * 32 * 4096) { g_Y[idx] = 0.0f; g_Z[idx] = 0.0f; }
}

extern "C" void kernel_launch(void* const* d_in, const int* in_sizes, int n_in,
                              void* d_out, int out_size)
{
    const float* X  = (const float*)d_in[0];
    const float* Wx = (const float*)d_in[1];
    const float* bx = (const float*)d_in[2];
    const float* Wy = (const float*)d_in[3];
    const float* by = (const float*)d_in[4];
    const float* Wz = (const float*)d_in[5];
    const float* bz = (const float*)d_in[6];
    float* out = (float*)d_out;

    static bool attr_done = false;
    if (!attr_done) {
        cudaFuncSetAttribute(conv_tc<0>, cudaFuncAttributeMaxDynamicSharedMemorySize, SMEM_SZ);
        cudaFuncSetAttribute(conv_tc<1>, cudaFuncAttributeMaxDynamicSharedMemorySize, SMEM_SZ);
        cudaFuncSetAttribute(conv_tc<2>, cudaFuncAttributeMaxDynamicSharedMemorySize, SMEM_SZ);
        attr_done = true;
    }

    u16* WH = nullptr; u16* WL = nullptr;
    cudaGetSymbolAddress((void**)&WH, g_WH);
    cudaGetSymbolAddress((void**)&WL, g_WL);

    // Per-replay prep (deterministic): weights -> bf16 hi/lo; reset state.
    prep_w<<<(256 * KPAD + 255) / 256, 256>>>(Wx, Wy, Wz);
    init_k<<<(8 * 32 * 4096 + 255) / 256, 256>>>();

    // Precompute all input convolutions (tensor cores).
    conv_tc<0><<<dim3(16, 4, 400), 256, SMEM_SZ>>>(X, WH, WL, bx, nullptr, 0);

    // Recurrence: 50 steps, 3 launches each.
    const u16* WyH = WH + (size_t)128 * KPAD;
    const u16* WyL = WL + (size_t)128 * KPAD;
    const u16* WzH = WH + (size_t)224 * KPAD;
    const u16* WzL = WL + (size_t)224 * KPAD;
    for (int t = 0; t < Tn; t++) {
        conv_tc<1><<<dim3(16, 3, 8), 256, SMEM_SZ>>>(nullptr, WyH, WyL, by, nullptr, t);
        elemZ_k<<<((8 * 32 * 4096) / 4 + 255) / 256, 256>>>(t);
        conv_tc<2><<<dim3(16, 1, 8), 256, SMEM_SZ>>>(nullptr, WzH, WzL, bz, out, t);
    }
}